// round 6
// baseline (speedup 1.0000x reference)
#include <cuda_runtime.h>

// out = clamp(floor(x * 16 + r) * (1/16), -8.0, 7.9375)
// WL=8, FL=4 -> sigma = 2^-4 (power of 2: *16 and *0.0625 are exact in fp32).
//
// HBM-streaming kernel at ~90% of 8 TB/s. This revision keeps the winning
// R3 configuration (one float4/thread, exact grid, single linear stream)
// and adds evict-first cache hints (__ldcs/__stcs): data has zero reuse,
// so L2 evict-first minimizes dirty-residency pressure. Isolated experiment —
// only the cache policy differs from the 217.6us/7221GB/s baseline.

__device__ __forceinline__ float quant1(float x, float r) {
    float q = floorf(fmaf(x, 16.0f, r)) * 0.0625f;
    q = fminf(q, 7.9375f);
    q = fmaxf(q, -8.0f);
    return q;
}

__global__ void __launch_bounds__(256) quant_kernel_v4(
    const float4* __restrict__ x,
    const float4* __restrict__ r,
    float4* __restrict__ out,
    int n4)
{
    int i = blockIdx.x * blockDim.x + threadIdx.x;
    if (i < n4) {
        float4 xv = __ldcs(x + i);
        float4 rv = __ldcs(r + i);
        float4 o;
        o.x = quant1(xv.x, rv.x);
        o.y = quant1(xv.y, rv.y);
        o.z = quant1(xv.z, rv.z);
        o.w = quant1(xv.w, rv.w);
        __stcs(out + i, o);
    }
}

__global__ void quant_kernel_tail(
    const float* __restrict__ x,
    const float* __restrict__ r,
    float* __restrict__ out,
    int start, int n)
{
    int i = start + blockIdx.x * blockDim.x + threadIdx.x;
    if (i < n) out[i] = quant1(x[i], r[i]);
}

extern "C" void kernel_launch(void* const* d_in, const int* in_sizes, int n_in,
                              void* d_out, int out_size) {
    const float* x = (const float*)d_in[0];
    const float* r = (const float*)d_in[1];
    float* out = (float*)d_out;
    int n = in_sizes[0];

    int n4 = n / 4;
    if (n4 > 0) {
        const int threads = 256;
        int blocks = (n4 + threads - 1) / threads;  // exact: 131072 for n=2^27
        quant_kernel_v4<<<blocks, threads>>>(
            (const float4*)x, (const float4*)r, (float4*)out, n4);
    }
    int rem_start = n4 * 4;
    int rem = n - rem_start;
    if (rem > 0) {
        quant_kernel_tail<<<(rem + 255) / 256, 256>>>(x, r, out, rem_start, n);
    }
}

// round 10
// speedup vs baseline: 1.0084x; 1.0084x over previous
#include <cuda_runtime.h>

// out = clamp(floor(x * 16 + r) * (1/16), -8.0, 7.9375)
// WL=8, FL=4 -> sigma = 2^-4 (power of 2: *16 and *0.0625 are exact in fp32).
//
// Converged HBM-streaming kernel (~90% of 8 TB/s; DRAM-pct 89-91, all compute
// pipes idle). Measured facts: cache hints neutral, MLP batching neutral,
// exact-grid single linear float4 stream is the winning pattern. This round
// re-runs the block=512 isolation (R7/R8 were infra failures, no data):
// halves CTA count, same per-warp access pattern.

__device__ __forceinline__ float quant1(float x, float r) {
    float q = floorf(fmaf(x, 16.0f, r)) * 0.0625f;
    q = fminf(q, 7.9375f);
    q = fmaxf(q, -8.0f);
    return q;
}

__global__ void __launch_bounds__(512) quant_kernel_v4(
    const float4* __restrict__ x,
    const float4* __restrict__ r,
    float4* __restrict__ out,
    int n4)
{
    int i = blockIdx.x * blockDim.x + threadIdx.x;
    if (i < n4) {
        float4 xv = x[i];
        float4 rv = r[i];
        float4 o;
        o.x = quant1(xv.x, rv.x);
        o.y = quant1(xv.y, rv.y);
        o.z = quant1(xv.z, rv.z);
        o.w = quant1(xv.w, rv.w);
        out[i] = o;
    }
}

__global__ void quant_kernel_tail(
    const float* __restrict__ x,
    const float* __restrict__ r,
    float* __restrict__ out,
    int start, int n)
{
    int i = start + blockIdx.x * blockDim.x + threadIdx.x;
    if (i < n) out[i] = quant1(x[i], r[i]);
}

extern "C" void kernel_launch(void* const* d_in, const int* in_sizes, int n_in,
                              void* d_out, int out_size) {
    const float* x = (const float*)d_in[0];
    const float* r = (const float*)d_in[1];
    float* out = (float*)d_out;
    int n = in_sizes[0];

    int n4 = n / 4;
    if (n4 > 0) {
        const int threads = 512;
        int blocks = (n4 + threads - 1) / threads;  // exact: 65536 for n=2^27
        quant_kernel_v4<<<blocks, threads>>>(
            (const float4*)x, (const float4*)r, (float4*)out, n4);
    }
    int rem_start = n4 * 4;
    int rem = n - rem_start;
    if (rem > 0) {
        quant_kernel_tail<<<(rem + 255) / 256, 256>>>(x, r, out, rem_start, n);
    }
}